// round 1
// baseline (speedup 1.0000x reference)
#include <cuda_runtime.h>

#define N_NODES  100000
#define N_EDGES  3200000
#define N_GRAPHS 256
#define HID      32
#define IN_DIM   6
#define BN_EPS   1e-5f

// ---------------- device scratch (no allocations allowed) ----------------
__device__ float g_ew[N_EDGES];
__device__ float g_deg[N_NODES];
__device__ float g_dinv[N_NODES];
__device__ float g_xw[N_NODES * HID];
__device__ float g_bufA[N_NODES * HID];
__device__ float g_bufB[N_NODES * HID];
__device__ float g_sums[N_GRAPHS * HID];
__device__ int   g_cnts[N_GRAPHS];

// Buffer selector: 0 -> g_bufA, 1 -> g_bufB, 2 -> external pointer (emb / x)
__device__ __forceinline__ float* buf_ptr(int which, float* ext) {
    return (which == 0) ? g_bufA : (which == 1) ? g_bufB : ext;
}
__device__ __forceinline__ const float* cbuf_ptr(int which, const float* ext) {
    return (which == 0) ? g_bufA : (which == 1) ? g_bufB : ext;
}

// ---------------- kernels ----------------

__global__ void k_zero() {
    int i = blockIdx.x * blockDim.x + threadIdx.x;
    if (i < N_NODES)          g_deg[i]  = 0.f;
    if (i < N_GRAPHS * HID)   g_sums[i] = 0.f;
    if (i < N_GRAPHS)         g_cnts[i] = 0;
}

// Per-edge gaussian kernel weight + degree accumulation.
__global__ void k_edgew(const int* __restrict__ ei,
                        const float* __restrict__ pos,
                        const float* __restrict__ ps1,
                        const float* __restrict__ ps2) {
    const int* row = ei;
    const int* col = ei + N_EDGES;
    float s1 = ps1[0], s2 = ps2[0];
    float s1sq = s1 * s1, s2sq = s2 * s2;
    int stride = gridDim.x * blockDim.x;
    for (int e = blockIdx.x * blockDim.x + threadIdx.x; e < N_EDGES; e += stride) {
        int r = row[e];
        int c = col[e];
        const float* pr = pos + (size_t)r * 6;
        const float* pc = pos + (size_t)c * 6;
        float d0 = pr[0] - pc[0];
        float d1 = pr[1] - pc[1];
        float d2 = pr[2] - pc[2];
        float D  = d0 * d0 + d1 * d1 + d2 * d2;
        float dot = pr[3] * pc[3] + pr[4] * pc[4] + pr[5] * pc[5];
        float t  = 1.0f - dot;
        float T  = t * t;
        float w  = expf(-(D * s1sq + T * s2sq));
        g_ew[e] = w;
        atomicAdd(&g_deg[c], w);
    }
}

__global__ void k_dinv() {
    int i = blockIdx.x * blockDim.x + threadIdx.x;
    if (i < N_NODES) {
        g_dinv[i] = rsqrtf(g_deg[i] + 1.0f);
    }
}

// Fused: [optional BN(g,be)+ReLU on input] -> xw = in @ W -> out = dinv^2*xw + b
// One warp per node; lane = output channel. W staged in shared.
__global__ void k_gemm(const float* __restrict__ ext_in, int in_which, int din,
                       const float* __restrict__ W,
                       const float* __restrict__ b,
                       const float* __restrict__ bng,
                       const float* __restrict__ bnb,
                       int apply_bn,
                       float* __restrict__ ext_out, int out_which) {
    __shared__ float Ws[32 * HID];
    const float* in = cbuf_ptr(in_which, ext_in);
    float* out = buf_ptr(out_which, ext_out);

    for (int i = threadIdx.x; i < din * HID; i += blockDim.x) Ws[i] = W[i];
    __syncthreads();

    int gwarp = (blockIdx.x * blockDim.x + threadIdx.x) >> 5;
    int lane  = threadIdx.x & 31;
    if (gwarp >= N_NODES) return;
    int n = gwarp;

    float hv = 0.f;
    if (lane < din) {
        hv = in[(size_t)n * din + lane];
        if (apply_bn) {
            float sc = bng[lane] * rsqrtf(1.0f + BN_EPS);
            hv = fmaxf(fmaf(hv, sc, bnb[lane]), 0.f);
        }
    }
    float acc = 0.f;
    #pragma unroll 8
    for (int k = 0; k < din; ++k) {
        acc = fmaf(__shfl_sync(0xffffffffu, hv, k), Ws[k * HID + lane], acc);
    }
    g_xw[(size_t)n * HID + lane] = acc;
    float di = g_dinv[n];
    out[(size_t)n * HID + lane] = fmaf(di * di, acc, b[lane]);
}

// Scatter: out[col] += dinv[row]*ew*dinv[col] * xw[row]. One warp per edge, lane = channel.
__global__ void k_scatter(const int* __restrict__ ei,
                          float* __restrict__ ext_out, int out_which) {
    float* out = buf_ptr(out_which, ext_out);
    const int* row = ei;
    const int* col = ei + N_EDGES;
    int t = blockIdx.x * blockDim.x + threadIdx.x;
    int lane = t & 31;
    int warps = (gridDim.x * blockDim.x) >> 5;
    for (int e = t >> 5; e < N_EDGES; e += warps) {
        int r = row[e];
        int c = col[e];
        float w = g_dinv[r] * g_ew[e] * g_dinv[c];
        float v = w * __ldg(&g_xw[(size_t)r * HID + lane]);
        atomicAdd(&out[(size_t)c * HID + lane], v);
    }
}

// Pool: segment sums over (sorted) batch. One warp per node, lane = channel.
__global__ void k_pool(const float* __restrict__ emb, const int* __restrict__ batch) {
    int t = blockIdx.x * blockDim.x + threadIdx.x;
    int lane = t & 31;
    int n = t >> 5;
    if (n >= N_NODES) return;
    int gidx = batch[n];
    atomicAdd(&g_sums[(size_t)gidx * HID + lane], emb[(size_t)n * HID + lane]);
    if (lane == 0) atomicAdd(&g_cnts[gidx], 1);
}

__global__ void k_pred(const float* __restrict__ Wout,
                       const float* __restrict__ bout,
                       float* __restrict__ pred) {
    int gI = threadIdx.x;  // 256 threads, one graph each
    if (gI >= N_GRAPHS) return;
    float cnt = fmaxf((float)g_cnts[gI], 1.0f);
    float inv = 1.0f / cnt;
    float acc = bout[0];
    #pragma unroll
    for (int k = 0; k < HID; ++k) {
        acc = fmaf(g_sums[gI * HID + k] * inv, Wout[k], acc);
    }
    pred[gI] = 1.0f / (1.0f + expf(-acc));
}

// ---------------- launcher ----------------
extern "C" void kernel_launch(void* const* d_in, const int* in_sizes, int n_in,
                              void* d_out, int out_size) {
    const float* x     = (const float*)d_in[0];
    const int*   ei    = (const int*)  d_in[1];
    const float* pos   = (const float*)d_in[2];
    const int*   batch = (const int*)  d_in[3];
    const float* s1    = (const float*)d_in[4];
    const float* s2    = (const float*)d_in[5];
    const float* W1 = (const float*)d_in[6];
    const float* b1 = (const float*)d_in[7];
    const float* W2 = (const float*)d_in[8];
    const float* b2 = (const float*)d_in[9];
    const float* W3 = (const float*)d_in[10];
    const float* b3 = (const float*)d_in[11];
    const float* W4 = (const float*)d_in[12];
    const float* b4 = (const float*)d_in[13];
    const float* g1 = (const float*)d_in[14];
    const float* be1= (const float*)d_in[15];
    const float* g2 = (const float*)d_in[16];
    const float* be2= (const float*)d_in[17];
    const float* g3 = (const float*)d_in[18];
    const float* be3= (const float*)d_in[19];
    const float* Wout = (const float*)d_in[20];
    const float* bout = (const float*)d_in[21];

    float* outp = (float*)d_out;
    float* emb  = outp;                           // [N_NODES, HID]
    float* pred = outp + (size_t)N_NODES * HID;   // [N_GRAPHS]

    const int ZB = (N_NODES + 255) / 256;
    const int GEMM_BLOCKS = (N_NODES * 32 + 255) / 256;  // one warp per node

    k_zero<<<ZB, 256>>>();
    k_edgew<<<4096, 256>>>(ei, pos, s1, s2);
    k_dinv<<<ZB, 256>>>();

    // Layer 1: in = x (din=6, no BN) -> bufA
    k_gemm<<<GEMM_BLOCKS, 256>>>(x, 2, IN_DIM, W1, b1, nullptr, nullptr, 0, nullptr, 0);
    k_scatter<<<8192, 256>>>(ei, nullptr, 0);
    // Layer 2: in = bufA (BN g1) -> bufB
    k_gemm<<<GEMM_BLOCKS, 256>>>(nullptr, 0, HID, W2, b2, g1, be1, 1, nullptr, 1);
    k_scatter<<<8192, 256>>>(ei, nullptr, 1);
    // Layer 3: in = bufB (BN g2) -> bufA
    k_gemm<<<GEMM_BLOCKS, 256>>>(nullptr, 1, HID, W3, b3, g2, be2, 1, nullptr, 0);
    k_scatter<<<8192, 256>>>(ei, nullptr, 0);
    // Layer 4: in = bufA (BN g3) -> emb (d_out)
    k_gemm<<<GEMM_BLOCKS, 256>>>(nullptr, 0, HID, W4, b4, g3, be3, 1, emb, 2);
    k_scatter<<<8192, 256>>>(ei, emb, 2);

    k_pool<<<GEMM_BLOCKS, 256>>>(emb, batch);
    k_pred<<<1, 256>>>(Wout, bout, pred);
}

// round 3
// speedup vs baseline: 1.4211x; 1.4211x over previous
#include <cuda_runtime.h>

#define N_NODES  100000
#define N_EDGES  3200000
#define N_GRAPHS 256
#define HID      32
#define IN_DIM   6
#define BN_EPS   1e-5f
#define FULL     0xffffffffu

// ---------------- device scratch (no allocations allowed) ----------------
__device__ float g_ew[N_EDGES];       // per-edge gaussian weight (edge order)
__device__ int   g_srow[N_EDGES];     // CSR: source row ids, sorted by col
__device__ float g_nrm[N_EDGES];      // CSR: norm weight dinv[r]*ew*dinv[c], sorted by col
__device__ float g_deg[N_NODES];
__device__ float g_dinv[N_NODES];
__device__ int   g_cnt[N_NODES];      // in-degree histogram
__device__ int   g_start[N_NODES];    // CSR start offsets
__device__ int   g_cursor[N_NODES];   // build cursors
__device__ float g_xwA[N_NODES * HID];
__device__ float g_xwB[N_NODES * HID];
__device__ float g_sums[N_GRAPHS * HID];
__device__ int   g_cnts[N_GRAPHS];

// Device-side buffer selector: 0 -> g_xwA, 1 -> g_xwB. (NEVER pass __device__
// symbols as kernel args from host — host symbol address != device address.)
__device__ __forceinline__ const float* in_buf(int which)  { return which ? g_xwB : g_xwA; }
__device__ __forceinline__ float*       out_buf(int which) { return which ? g_xwB : g_xwA; }

// ---------------- kernels ----------------

__global__ void k_zero() {
    int i = blockIdx.x * blockDim.x + threadIdx.x;
    if (i < N_NODES) { g_deg[i] = 0.f; g_cnt[i] = 0; }
    if (i < N_GRAPHS * HID) g_sums[i] = 0.f;
    if (i < N_GRAPHS)       g_cnts[i] = 0;
}

// Edge weights + weighted degree + integer in-degree histogram.
__global__ void k_edgew(const int* __restrict__ ei,
                        const float* __restrict__ pos,
                        const float* __restrict__ ps1,
                        const float* __restrict__ ps2) {
    const int* row = ei;
    const int* col = ei + N_EDGES;
    float s1 = ps1[0], s2 = ps2[0];
    float s1sq = s1 * s1, s2sq = s2 * s2;
    int stride = gridDim.x * blockDim.x;
    for (int e = blockIdx.x * blockDim.x + threadIdx.x; e < N_EDGES; e += stride) {
        int r = row[e];
        int c = col[e];
        const float* pr = pos + (size_t)r * 6;
        const float* pc = pos + (size_t)c * 6;
        float d0 = pr[0] - pc[0];
        float d1 = pr[1] - pc[1];
        float d2 = pr[2] - pc[2];
        float D  = d0 * d0 + d1 * d1 + d2 * d2;
        float dot = pr[3] * pc[3] + pr[4] * pc[4] + pr[5] * pc[5];
        float t  = 1.0f - dot;
        float w  = __expf(-(D * s1sq + t * t * s2sq));
        g_ew[e] = w;
        atomicAdd(&g_deg[c], w);
        atomicAdd(&g_cnt[c], 1);
    }
}

__global__ void k_dinv() {
    int i = blockIdx.x * blockDim.x + threadIdx.x;
    if (i < N_NODES) g_dinv[i] = rsqrtf(g_deg[i] + 1.0f);
}

// Single-block exclusive scan of g_cnt -> g_start (+ cursor copy). 1024 threads.
__global__ void k_scan() {
    const int T  = 1024;
    const int CH = (N_NODES + T - 1) / T;  // 98
    int t  = threadIdx.x;
    int lo = t * CH;
    int hi = min(lo + CH, N_NODES);
    int s  = 0;
    for (int i = lo; i < hi; ++i) s += g_cnt[i];
    __shared__ int sh[T];
    sh[t] = s;
    __syncthreads();
    for (int off = 1; off < T; off <<= 1) {
        int v = (t >= off) ? sh[t - off] : 0;
        __syncthreads();
        sh[t] += v;
        __syncthreads();
    }
    int run = (t == 0) ? 0 : sh[t - 1];
    for (int i = lo; i < hi; ++i) {
        int c = g_cnt[i];
        g_start[i]  = run;
        g_cursor[i] = run;
        run += c;
    }
}

// Bucket sort edges by col; precompute layer-invariant norm weight.
__global__ void k_build(const int* __restrict__ ei) {
    const int* row = ei;
    const int* col = ei + N_EDGES;
    int stride = gridDim.x * blockDim.x;
    for (int e = blockIdx.x * blockDim.x + threadIdx.x; e < N_EDGES; e += stride) {
        int r = row[e];
        int c = col[e];
        float nrm = g_dinv[r] * g_ew[e] * g_dinv[c];
        int p = atomicAdd(&g_cursor[c], 1);
        g_srow[p] = r;
        g_nrm[p]  = nrm;
    }
}

// Layer-1 GEMM: xwA = x @ W1. Warp per node, lane = out channel.
__global__ void k_gemm1(const float* __restrict__ x, const float* __restrict__ W1) {
    __shared__ float Ws[IN_DIM * HID];
    for (int i = threadIdx.x; i < IN_DIM * HID; i += blockDim.x) Ws[i] = W1[i];
    __syncthreads();
    int n = (blockIdx.x * blockDim.x + threadIdx.x) >> 5;
    int lane = threadIdx.x & 31;
    if (n >= N_NODES) return;
    float hv = (lane < IN_DIM) ? x[(size_t)n * IN_DIM + lane] : 0.f;
    float acc = 0.f;
    #pragma unroll
    for (int k = 0; k < IN_DIM; ++k)
        acc = fmaf(__shfl_sync(FULL, hv, k), Ws[k * HID + lane], acc);
    g_xwA[(size_t)n * HID + lane] = acc;
}

// Fused gather layer: conv[n] = b + dinv[n]^2*xw[n] + sum_{e in CSR[n]} nrm_e * xw[srow_e]
// If FUSE_NEXT: apply BN(g,be)+ReLU then 32x32 GEMM with Wnext -> out_buf(out_which).
// Else: write emb (real device ptr from d_out) and do fused pool atomics.
template <int FUSE_NEXT>
__global__ void k_gather(int in_which, int out_which,
                         const float* __restrict__ b,
                         const float* __restrict__ bng,
                         const float* __restrict__ bnb,
                         const float* __restrict__ Wnext,
                         float* __restrict__ emb,
                         const int* __restrict__ batch) {
    __shared__ float Ws[HID * HID];
    if (FUSE_NEXT) {
        for (int i = threadIdx.x; i < HID * HID; i += blockDim.x) Ws[i] = Wnext[i];
        __syncthreads();
    }
    const float* xw = in_buf(in_which);

    int n = (blockIdx.x * blockDim.x + threadIdx.x) >> 5;
    int lane = threadIdx.x & 31;
    if (n >= N_NODES) return;

    int start = g_start[n];
    int end   = start + g_cnt[n];
    float di  = g_dinv[n];
    float acc = fmaf(di * di, __ldg(&xw[(size_t)n * HID + lane]), b[lane]);

    for (int base = start; base < end; base += 32) {
        int rem = end - base;
        int m   = rem < 32 ? rem : 32;
        int   rl = (lane < m) ? __ldg(&g_srow[base + lane]) : 0;
        float wl = (lane < m) ? __ldg(&g_nrm[base + lane]) : 0.f;
        #pragma unroll 4
        for (int j = 0; j < m; ++j) {
            int   rj = __shfl_sync(FULL, rl, j);
            float wj = __shfl_sync(FULL, wl, j);
            acc = fmaf(wj, __ldg(&xw[(size_t)rj * HID + lane]), acc);
        }
    }

    if (FUSE_NEXT) {
        float sc = bng[lane] * rsqrtf(1.0f + BN_EPS);
        float h  = fmaxf(fmaf(acc, sc, bnb[lane]), 0.f);
        float o  = 0.f;
        #pragma unroll
        for (int k = 0; k < HID; ++k)
            o = fmaf(__shfl_sync(FULL, h, k), Ws[k * HID + lane], o);
        out_buf(out_which)[(size_t)n * HID + lane] = o;
    } else {
        emb[(size_t)n * HID + lane] = acc;
        int gidx = batch[n];
        atomicAdd(&g_sums[(size_t)gidx * HID + lane], acc);
        if (lane == 0) atomicAdd(&g_cnts[gidx], 1);
    }
}

__global__ void k_pred(const float* __restrict__ Wout,
                       const float* __restrict__ bout,
                       float* __restrict__ pred) {
    int gI = threadIdx.x;
    if (gI >= N_GRAPHS) return;
    float cnt = fmaxf((float)g_cnts[gI], 1.0f);
    float inv = 1.0f / cnt;
    float acc = bout[0];
    #pragma unroll
    for (int k = 0; k < HID; ++k)
        acc = fmaf(g_sums[gI * HID + k] * inv, Wout[k], acc);
    pred[gI] = 1.0f / (1.0f + expf(-acc));
}

// ---------------- launcher ----------------
extern "C" void kernel_launch(void* const* d_in, const int* in_sizes, int n_in,
                              void* d_out, int out_size) {
    const float* x     = (const float*)d_in[0];
    const int*   ei    = (const int*)  d_in[1];
    const float* pos   = (const float*)d_in[2];
    const int*   batch = (const int*)  d_in[3];
    const float* s1    = (const float*)d_in[4];
    const float* s2    = (const float*)d_in[5];
    const float* W1 = (const float*)d_in[6];
    const float* b1 = (const float*)d_in[7];
    const float* W2 = (const float*)d_in[8];
    const float* b2 = (const float*)d_in[9];
    const float* W3 = (const float*)d_in[10];
    const float* b3 = (const float*)d_in[11];
    const float* W4 = (const float*)d_in[12];
    const float* b4 = (const float*)d_in[13];
    const float* g1 = (const float*)d_in[14];
    const float* be1= (const float*)d_in[15];
    const float* g2 = (const float*)d_in[16];
    const float* be2= (const float*)d_in[17];
    const float* g3 = (const float*)d_in[18];
    const float* be3= (const float*)d_in[19];
    const float* Wout = (const float*)d_in[20];
    const float* bout = (const float*)d_in[21];

    float* outp = (float*)d_out;
    float* emb  = outp;                           // [N_NODES, HID]
    float* pred = outp + (size_t)N_NODES * HID;   // [N_GRAPHS]

    const int ZB = (N_NODES + 255) / 256;
    const int NODE_WARP_BLOCKS = (N_NODES * 32 + 255) / 256;

    k_zero <<<ZB, 256>>>();
    k_edgew<<<4096, 256>>>(ei, pos, s1, s2);
    k_dinv <<<ZB, 256>>>();
    k_scan <<<1, 1024>>>();
    k_build<<<4096, 256>>>(ei);

    k_gemm1<<<NODE_WARP_BLOCKS, 256>>>(x, W1);

    // Layer 1 gather (in=A) + BN1 + GEMM(W2) -> B
    k_gather<1><<<NODE_WARP_BLOCKS, 256>>>(0, 1, b1, g1, be1, W2, nullptr, nullptr);
    // Layer 2 gather (in=B) + BN2 + GEMM(W3) -> A
    k_gather<1><<<NODE_WARP_BLOCKS, 256>>>(1, 0, b2, g2, be2, W3, nullptr, nullptr);
    // Layer 3 gather (in=A) + BN3 + GEMM(W4) -> B
    k_gather<1><<<NODE_WARP_BLOCKS, 256>>>(0, 1, b3, g3, be3, W4, nullptr, nullptr);
    // Layer 4 gather (in=B) -> emb, fused pool
    k_gather<0><<<NODE_WARP_BLOCKS, 256>>>(1, 0, b4, nullptr, nullptr, nullptr, emb, batch);

    k_pred<<<1, 256>>>(Wout, bout, pred);
}

// round 4
// speedup vs baseline: 1.8560x; 1.3060x over previous
#include <cuda_runtime.h>

#define N_NODES  100000
#define N_EDGES  3200000
#define N_GRAPHS 256
#define HID      32
#define IN_DIM   6
#define BN_EPS   1e-5f
#define FULL     0xffffffffu

// multi-block scan config: 125 blocks x 800 elements = 100000 exactly
#define SCAN_BLOCKS 125
#define SCAN_CHUNK  800
#define SCAN_T      256
#define SCAN_PT     4      // ceil(800/256) -> 4 elems per thread (some idle)

// ---------------- device scratch (no allocations allowed) ----------------
__device__ float g_ew[N_EDGES];       // per-edge gaussian weight (edge order)
__device__ int   g_srow[N_EDGES];     // CSR: source row ids, sorted by col
__device__ float g_nrm[N_EDGES];      // CSR: norm weight dinv[r]*ew*dinv[c], sorted by col
__device__ float g_deg[N_NODES];
__device__ float g_dinv[N_NODES];
__device__ int   g_cnt[N_NODES];      // in-degree histogram
__device__ int   g_start[N_NODES];    // CSR start offsets
__device__ int   g_cursor[N_NODES];   // build cursors
__device__ int   g_bsum[SCAN_BLOCKS]; // per-block sums
__device__ int   g_boff[SCAN_BLOCKS]; // per-block exclusive offsets
__device__ float g_xwA[N_NODES * HID];
__device__ float g_xwB[N_NODES * HID];
__device__ float g_sums[N_GRAPHS * HID];
__device__ int   g_cnts[N_GRAPHS];

// Device-side buffer selector: 0 -> g_xwA, 1 -> g_xwB. (NEVER pass __device__
// symbols as kernel args from host — host symbol address != device address.)
__device__ __forceinline__ const float* in_buf(int which)  { return which ? g_xwB : g_xwA; }
__device__ __forceinline__ float*       out_buf(int which) { return which ? g_xwB : g_xwA; }

// ---------------- kernels ----------------

__global__ void k_zero() {
    int i = blockIdx.x * blockDim.x + threadIdx.x;
    if (i < N_NODES) { g_deg[i] = 0.f; g_cnt[i] = 0; }
    if (i < N_GRAPHS * HID) g_sums[i] = 0.f;
    if (i < N_GRAPHS)       g_cnts[i] = 0;
}

// Edge weights + weighted degree + integer in-degree histogram.
__global__ void k_edgew(const int* __restrict__ ei,
                        const float* __restrict__ pos,
                        const float* __restrict__ ps1,
                        const float* __restrict__ ps2) {
    const int* row = ei;
    const int* col = ei + N_EDGES;
    float s1 = ps1[0], s2 = ps2[0];
    float s1sq = s1 * s1, s2sq = s2 * s2;
    int stride = gridDim.x * blockDim.x;
    for (int e = blockIdx.x * blockDim.x + threadIdx.x; e < N_EDGES; e += stride) {
        int r = row[e];
        int c = col[e];
        const float* pr = pos + (size_t)r * 6;
        const float* pc = pos + (size_t)c * 6;
        float d0 = pr[0] - pc[0];
        float d1 = pr[1] - pc[1];
        float d2 = pr[2] - pc[2];
        float D  = d0 * d0 + d1 * d1 + d2 * d2;
        float dot = pr[3] * pc[3] + pr[4] * pc[4] + pr[5] * pc[5];
        float t  = 1.0f - dot;
        float w  = __expf(-(D * s1sq + t * t * s2sq));
        g_ew[e] = w;
        atomicAdd(&g_deg[c], w);
        atomicAdd(&g_cnt[c], 1);
    }
}

__global__ void k_dinv() {
    int i = blockIdx.x * blockDim.x + threadIdx.x;
    if (i < N_NODES) g_dinv[i] = rsqrtf(g_deg[i] + 1.0f);
}

// ---- 3-phase multi-block exclusive scan of g_cnt -> g_start / g_cursor ----

// Phase A: per-block sums.
__global__ void k_scanA() {
    int blk = blockIdx.x, t = threadIdx.x;
    int lo = blk * SCAN_CHUNK;
    int base = lo + t * SCAN_PT;
    int s = 0;
    #pragma unroll
    for (int i = 0; i < SCAN_PT; ++i) {
        int idx = base + i;
        if (idx < lo + SCAN_CHUNK && idx < N_NODES) s += g_cnt[idx];
    }
    __shared__ int sh[SCAN_T];
    sh[t] = s;
    __syncthreads();
    #pragma unroll
    for (int off = SCAN_T / 2; off > 0; off >>= 1) {
        if (t < off) sh[t] += sh[t + off];
        __syncthreads();
    }
    if (t == 0) g_bsum[blk] = sh[0];
}

// Phase B: single small block scans the 125 block sums (exclusive).
__global__ void k_scanB() {
    __shared__ int sh[SCAN_BLOCKS];
    int t = threadIdx.x;
    if (t < SCAN_BLOCKS) sh[t] = g_bsum[t];
    __syncthreads();
    if (t == 0) {
        int run = 0;
        #pragma unroll 5
        for (int i = 0; i < SCAN_BLOCKS; ++i) {
            int v = sh[i];
            sh[i] = run;
            run += v;
        }
    }
    __syncthreads();
    if (t < SCAN_BLOCKS) g_boff[t] = sh[t];
}

// Phase C: local exclusive scan within each block + global offset.
__global__ void k_scanC() {
    int blk = blockIdx.x, t = threadIdx.x;
    int lo = blk * SCAN_CHUNK;
    int base = lo + t * SCAN_PT;
    int v[SCAN_PT];
    int s = 0;
    #pragma unroll
    for (int i = 0; i < SCAN_PT; ++i) {
        int idx = base + i;
        v[i] = (idx < lo + SCAN_CHUNK && idx < N_NODES) ? g_cnt[idx] : 0;
        s += v[i];
    }
    __shared__ int sh[SCAN_T];
    sh[t] = s;
    __syncthreads();
    // Hillis-Steele inclusive scan over thread sums
    #pragma unroll
    for (int off = 1; off < SCAN_T; off <<= 1) {
        int add = (t >= off) ? sh[t - off] : 0;
        __syncthreads();
        sh[t] += add;
        __syncthreads();
    }
    int run = g_boff[blk] + ((t == 0) ? 0 : sh[t - 1]);
    #pragma unroll
    for (int i = 0; i < SCAN_PT; ++i) {
        int idx = base + i;
        if (idx < lo + SCAN_CHUNK && idx < N_NODES) {
            g_start[idx]  = run;
            g_cursor[idx] = run;
            run += v[i];
        }
    }
}

// Bucket sort edges by col; precompute layer-invariant norm weight.
__global__ void k_build(const int* __restrict__ ei) {
    const int* row = ei;
    const int* col = ei + N_EDGES;
    int stride = gridDim.x * blockDim.x;
    for (int e = blockIdx.x * blockDim.x + threadIdx.x; e < N_EDGES; e += stride) {
        int r = row[e];
        int c = col[e];
        float nrm = g_dinv[r] * g_ew[e] * g_dinv[c];
        int p = atomicAdd(&g_cursor[c], 1);
        g_srow[p] = r;
        g_nrm[p]  = nrm;
    }
}

// Layer-1 GEMM: xwA = x @ W1. Warp per node, lane = out channel.
__global__ void k_gemm1(const float* __restrict__ x, const float* __restrict__ W1) {
    __shared__ float Ws[IN_DIM * HID];
    for (int i = threadIdx.x; i < IN_DIM * HID; i += blockDim.x) Ws[i] = W1[i];
    __syncthreads();
    int n = (blockIdx.x * blockDim.x + threadIdx.x) >> 5;
    int lane = threadIdx.x & 31;
    if (n >= N_NODES) return;
    float hv = (lane < IN_DIM) ? x[(size_t)n * IN_DIM + lane] : 0.f;
    float acc = 0.f;
    #pragma unroll
    for (int k = 0; k < IN_DIM; ++k)
        acc = fmaf(__shfl_sync(FULL, hv, k), Ws[k * HID + lane], acc);
    g_xwA[(size_t)n * HID + lane] = acc;
}

// Fused gather layer: conv[n] = b + dinv[n]^2*xw[n] + sum_{e in CSR[n]} nrm_e * xw[srow_e]
// If FUSE_NEXT: apply BN(g,be)+ReLU then 32x32 GEMM with Wnext -> out_buf(out_which).
// Else: write emb (real device ptr from d_out) and do fused pool atomics.
template <int FUSE_NEXT>
__global__ void k_gather(int in_which, int out_which,
                         const float* __restrict__ b,
                         const float* __restrict__ bng,
                         const float* __restrict__ bnb,
                         const float* __restrict__ Wnext,
                         float* __restrict__ emb,
                         const int* __restrict__ batch) {
    __shared__ float Ws[HID * HID];
    if (FUSE_NEXT) {
        for (int i = threadIdx.x; i < HID * HID; i += blockDim.x) Ws[i] = Wnext[i];
        __syncthreads();
    }
    const float* xw = in_buf(in_which);

    int n = (blockIdx.x * blockDim.x + threadIdx.x) >> 5;
    int lane = threadIdx.x & 31;
    if (n >= N_NODES) return;

    int start = g_start[n];
    int end   = start + g_cnt[n];
    float di  = g_dinv[n];
    float acc = fmaf(di * di, __ldg(&xw[(size_t)n * HID + lane]), b[lane]);

    for (int base = start; base < end; base += 32) {
        int rem = end - base;
        int m   = rem < 32 ? rem : 32;
        int   rl = (lane < m) ? __ldg(&g_srow[base + lane]) : 0;
        float wl = (lane < m) ? __ldg(&g_nrm[base + lane]) : 0.f;
        #pragma unroll 4
        for (int j = 0; j < m; ++j) {
            int   rj = __shfl_sync(FULL, rl, j);
            float wj = __shfl_sync(FULL, wl, j);
            acc = fmaf(wj, __ldg(&xw[(size_t)rj * HID + lane]), acc);
        }
    }

    if (FUSE_NEXT) {
        float sc = bng[lane] * rsqrtf(1.0f + BN_EPS);
        float h  = fmaxf(fmaf(acc, sc, bnb[lane]), 0.f);
        float o  = 0.f;
        #pragma unroll
        for (int k = 0; k < HID; ++k)
            o = fmaf(__shfl_sync(FULL, h, k), Ws[k * HID + lane], o);
        out_buf(out_which)[(size_t)n * HID + lane] = o;
    } else {
        emb[(size_t)n * HID + lane] = acc;
        int gidx = batch[n];
        atomicAdd(&g_sums[(size_t)gidx * HID + lane], acc);
        if (lane == 0) atomicAdd(&g_cnts[gidx], 1);
    }
}

__global__ void k_pred(const float* __restrict__ Wout,
                       const float* __restrict__ bout,
                       float* __restrict__ pred) {
    int gI = threadIdx.x;
    if (gI >= N_GRAPHS) return;
    float cnt = fmaxf((float)g_cnts[gI], 1.0f);
    float inv = 1.0f / cnt;
    float acc = bout[0];
    #pragma unroll
    for (int k = 0; k < HID; ++k)
        acc = fmaf(g_sums[gI * HID + k] * inv, Wout[k], acc);
    pred[gI] = 1.0f / (1.0f + expf(-acc));
}

// ---------------- launcher ----------------
extern "C" void kernel_launch(void* const* d_in, const int* in_sizes, int n_in,
                              void* d_out, int out_size) {
    const float* x     = (const float*)d_in[0];
    const int*   ei    = (const int*)  d_in[1];
    const float* pos   = (const float*)d_in[2];
    const int*   batch = (const int*)  d_in[3];
    const float* s1    = (const float*)d_in[4];
    const float* s2    = (const float*)d_in[5];
    const float* W1 = (const float*)d_in[6];
    const float* b1 = (const float*)d_in[7];
    const float* W2 = (const float*)d_in[8];
    const float* b2 = (const float*)d_in[9];
    const float* W3 = (const float*)d_in[10];
    const float* b3 = (const float*)d_in[11];
    const float* W4 = (const float*)d_in[12];
    const float* b4 = (const float*)d_in[13];
    const float* g1 = (const float*)d_in[14];
    const float* be1= (const float*)d_in[15];
    const float* g2 = (const float*)d_in[16];
    const float* be2= (const float*)d_in[17];
    const float* g3 = (const float*)d_in[18];
    const float* be3= (const float*)d_in[19];
    const float* Wout = (const float*)d_in[20];
    const float* bout = (const float*)d_in[21];

    float* outp = (float*)d_out;
    float* emb  = outp;                           // [N_NODES, HID]
    float* pred = outp + (size_t)N_NODES * HID;   // [N_GRAPHS]

    const int ZB = (N_NODES + 255) / 256;
    const int NODE_WARP_BLOCKS = (N_NODES * 32 + 255) / 256;

    k_zero <<<ZB, 256>>>();
    k_edgew<<<4096, 256>>>(ei, pos, s1, s2);
    k_dinv <<<ZB, 256>>>();
    k_scanA<<<SCAN_BLOCKS, SCAN_T>>>();
    k_scanB<<<1, 128>>>();
    k_scanC<<<SCAN_BLOCKS, SCAN_T>>>();
    k_build<<<4096, 256>>>(ei);

    k_gemm1<<<NODE_WARP_BLOCKS, 256>>>(x, W1);

    // Layer 1 gather (in=A) + BN1 + GEMM(W2) -> B
    k_gather<1><<<NODE_WARP_BLOCKS, 256>>>(0, 1, b1, g1, be1, W2, nullptr, nullptr);
    // Layer 2 gather (in=B) + BN2 + GEMM(W3) -> A
    k_gather<1><<<NODE_WARP_BLOCKS, 256>>>(1, 0, b2, g2, be2, W3, nullptr, nullptr);
    // Layer 3 gather (in=A) + BN3 + GEMM(W4) -> B
    k_gather<1><<<NODE_WARP_BLOCKS, 256>>>(0, 1, b3, g3, be3, W4, nullptr, nullptr);
    // Layer 4 gather (in=B) -> emb, fused pool
    k_gather<0><<<NODE_WARP_BLOCKS, 256>>>(1, 0, b4, nullptr, nullptr, nullptr, emb, batch);

    k_pred<<<1, 256>>>(Wout, bout, pred);
}

// round 5
// speedup vs baseline: 2.3295x; 1.2552x over previous
#include <cuda_runtime.h>

#define N_NODES  100000
#define N_EDGES  3200000
#define N_GRAPHS 256
#define HID      32
#define IN_DIM   6
#define BN_EPS   1e-5f
#define FULL     0xffffffffu

// multi-block scan config: 125 blocks x 800 elements = 100000 exactly
#define SCAN_BLOCKS 125
#define SCAN_CHUNK  800
#define SCAN_T      256
#define SCAN_PT     4

// ---------------- device scratch (no allocations allowed) ----------------
__device__ float g_ew[N_EDGES];               // per-edge gaussian weight (edge order)
__device__ __align__(16) int2 g_edge[N_EDGES];// CSR: {srow, nrm_as_int}, sorted by col
__device__ float g_deg[N_NODES];
__device__ float g_dinv[N_NODES];
__device__ int   g_cnt[N_NODES];
__device__ int   g_start[N_NODES];
__device__ int   g_cursor[N_NODES];
__device__ int   g_bsum[SCAN_BLOCKS];
__device__ int   g_boff[SCAN_BLOCKS];
__device__ __align__(16) float g_xwA[N_NODES * HID];
__device__ __align__(16) float g_xwB[N_NODES * HID];
__device__ float g_sums[N_GRAPHS * HID];
__device__ int   g_cnts[N_GRAPHS];

__device__ __forceinline__ const float* in_buf(int which)  { return which ? g_xwB : g_xwA; }
__device__ __forceinline__ float*       out_buf(int which) { return which ? g_xwB : g_xwA; }

// ---------------- kernels ----------------

__global__ void k_zero() {
    int i = blockIdx.x * blockDim.x + threadIdx.x;
    if (i < N_NODES) { g_deg[i] = 0.f; g_cnt[i] = 0; }
    if (i < N_GRAPHS * HID) g_sums[i] = 0.f;
    if (i < N_GRAPHS)       g_cnts[i] = 0;
}

// Edge weights + weighted degree + integer in-degree histogram. float2 pos loads.
__global__ void k_edgew(const int* __restrict__ ei,
                        const float* __restrict__ pos,
                        const float* __restrict__ ps1,
                        const float* __restrict__ ps2) {
    const int* row = ei;
    const int* col = ei + N_EDGES;
    const float2* pos2 = (const float2*)pos;
    float s1 = ps1[0], s2 = ps2[0];
    float s1sq = s1 * s1, s2sq = s2 * s2;
    int stride = gridDim.x * blockDim.x;
    for (int e = blockIdx.x * blockDim.x + threadIdx.x; e < N_EDGES; e += stride) {
        int r = row[e];
        int c = col[e];
        float2 r0 = __ldg(&pos2[3 * r]);
        float2 r1 = __ldg(&pos2[3 * r + 1]);
        float2 r2 = __ldg(&pos2[3 * r + 2]);
        float2 c0 = __ldg(&pos2[3 * c]);
        float2 c1 = __ldg(&pos2[3 * c + 1]);
        float2 c2 = __ldg(&pos2[3 * c + 2]);
        float d0 = r0.x - c0.x;
        float d1 = r0.y - c0.y;
        float d2 = r1.x - c1.x;
        float D  = d0 * d0 + d1 * d1 + d2 * d2;
        float dot = r1.y * c1.y + r2.x * c2.x + r2.y * c2.y;
        float t  = 1.0f - dot;
        float w  = __expf(-(D * s1sq + t * t * s2sq));
        g_ew[e] = w;
        atomicAdd(&g_deg[c], w);
        atomicAdd(&g_cnt[c], 1);
    }
}

__global__ void k_dinv() {
    int i = blockIdx.x * blockDim.x + threadIdx.x;
    if (i < N_NODES) g_dinv[i] = rsqrtf(g_deg[i] + 1.0f);
}

// ---- 3-phase multi-block exclusive scan of g_cnt -> g_start / g_cursor ----
__global__ void k_scanA() {
    int blk = blockIdx.x, t = threadIdx.x;
    int lo = blk * SCAN_CHUNK;
    int base = lo + t * SCAN_PT;
    int s = 0;
    #pragma unroll
    for (int i = 0; i < SCAN_PT; ++i) {
        int idx = base + i;
        if (idx < lo + SCAN_CHUNK && idx < N_NODES) s += g_cnt[idx];
    }
    __shared__ int sh[SCAN_T];
    sh[t] = s;
    __syncthreads();
    #pragma unroll
    for (int off = SCAN_T / 2; off > 0; off >>= 1) {
        if (t < off) sh[t] += sh[t + off];
        __syncthreads();
    }
    if (t == 0) g_bsum[blk] = sh[0];
}

__global__ void k_scanB() {
    __shared__ int sh[SCAN_BLOCKS];
    int t = threadIdx.x;
    if (t < SCAN_BLOCKS) sh[t] = g_bsum[t];
    __syncthreads();
    if (t == 0) {
        int run = 0;
        for (int i = 0; i < SCAN_BLOCKS; ++i) {
            int v = sh[i];
            sh[i] = run;
            run += v;
        }
    }
    __syncthreads();
    if (t < SCAN_BLOCKS) g_boff[t] = sh[t];
}

__global__ void k_scanC() {
    int blk = blockIdx.x, t = threadIdx.x;
    int lo = blk * SCAN_CHUNK;
    int base = lo + t * SCAN_PT;
    int v[SCAN_PT];
    int s = 0;
    #pragma unroll
    for (int i = 0; i < SCAN_PT; ++i) {
        int idx = base + i;
        v[i] = (idx < lo + SCAN_CHUNK && idx < N_NODES) ? g_cnt[idx] : 0;
        s += v[i];
    }
    __shared__ int sh[SCAN_T];
    sh[t] = s;
    __syncthreads();
    #pragma unroll
    for (int off = 1; off < SCAN_T; off <<= 1) {
        int add = (t >= off) ? sh[t - off] : 0;
        __syncthreads();
        sh[t] += add;
        __syncthreads();
    }
    int run = g_boff[blk] + ((t == 0) ? 0 : sh[t - 1]);
    #pragma unroll
    for (int i = 0; i < SCAN_PT; ++i) {
        int idx = base + i;
        if (idx < lo + SCAN_CHUNK && idx < N_NODES) {
            g_start[idx]  = run;
            g_cursor[idx] = run;
            run += v[i];
        }
    }
}

// Bucket sort edges by col; packed {srow, nrm} record, single 8B store.
__global__ void k_build(const int* __restrict__ ei) {
    const int* row = ei;
    const int* col = ei + N_EDGES;
    int stride = gridDim.x * blockDim.x;
    for (int e = blockIdx.x * blockDim.x + threadIdx.x; e < N_EDGES; e += stride) {
        int r = row[e];
        int c = col[e];
        float nrm = g_dinv[r] * g_ew[e] * g_dinv[c];
        int p = atomicAdd(&g_cursor[c], 1);
        g_edge[p] = make_int2(r, __float_as_int(nrm));
    }
}

// Layer-1 GEMM: xwA = x @ W1. Warp per node, lane = out channel.
__global__ void k_gemm1(const float* __restrict__ x, const float* __restrict__ W1) {
    __shared__ float Ws[IN_DIM * HID];
    for (int i = threadIdx.x; i < IN_DIM * HID; i += blockDim.x) Ws[i] = W1[i];
    __syncthreads();
    int n = (blockIdx.x * blockDim.x + threadIdx.x) >> 5;
    int lane = threadIdx.x & 31;
    if (n >= N_NODES) return;
    float hv = (lane < IN_DIM) ? x[(size_t)n * IN_DIM + lane] : 0.f;
    float acc = 0.f;
    #pragma unroll
    for (int k = 0; k < IN_DIM; ++k)
        acc = fmaf(__shfl_sync(FULL, hv, k), Ws[k * HID + lane], acc);
    g_xwA[(size_t)n * HID + lane] = acc;
}

// Fused gather layer (float4 path): warp per node; group g=lane>>3 handles edge 4j+g,
// each lane accumulates 4 channels (sub=lane&7). Cross-group shfl_xor reduce, smem
// transpose to scalar, then BN+ReLU+GEMM(Wnext) epilogue or emb+pool.
template <int FUSE_NEXT>
__global__ void k_gather(int in_which, int out_which,
                         const float* __restrict__ b,
                         const float* __restrict__ bng,
                         const float* __restrict__ bnb,
                         const float* __restrict__ Wnext,
                         float* __restrict__ emb,
                         const int* __restrict__ batch) {
    __shared__ float Ws[HID * HID];
    __shared__ int2  sh_e[8][32];
    __shared__ float sh_h[8][32];
    if (FUSE_NEXT) {
        for (int i = threadIdx.x; i < HID * HID; i += blockDim.x) Ws[i] = Wnext[i];
        __syncthreads();
    }
    const float4* xw4 = (const float4*)in_buf(in_which);

    int warp = threadIdx.x >> 5;
    int lane = threadIdx.x & 31;
    int n = (blockIdx.x * blockDim.x + threadIdx.x) >> 5;
    if (n >= N_NODES) return;
    int grp = lane >> 3;
    int sub = lane & 7;

    int start = g_start[n];
    int cnt   = g_cnt[n];
    int end   = start + cnt;

    float4 acc = make_float4(0.f, 0.f, 0.f, 0.f);

    for (int base = start; base < end; base += 32) {
        int m = end - base; if (m > 32) m = 32;
        if (lane < m) sh_e[warp][lane] = __ldg(&g_edge[base + lane]);
        __syncwarp();
        int iters = (m + 3) >> 2;
        for (int j = 0; j < iters; ++j) {
            int eidx = j * 4 + grp;
            int  sel = eidx < m ? eidx : m - 1;
            int2 e   = sh_e[warp][sel];
            float w  = (eidx < m) ? __int_as_float(e.y) : 0.f;
            float4 v = __ldg(&xw4[(size_t)e.x * 8 + sub]);
            acc.x = fmaf(w, v.x, acc.x);
            acc.y = fmaf(w, v.y, acc.y);
            acc.z = fmaf(w, v.z, acc.z);
            acc.w = fmaf(w, v.w, acc.w);
        }
        __syncwarp();
    }

    // reduce partials across the 4 groups
    #pragma unroll
    for (int off = 8; off < 32; off <<= 1) {
        acc.x += __shfl_xor_sync(FULL, acc.x, off);
        acc.y += __shfl_xor_sync(FULL, acc.y, off);
        acc.z += __shfl_xor_sync(FULL, acc.z, off);
        acc.w += __shfl_xor_sync(FULL, acc.w, off);
    }

    // self term + bias (once, post-reduction; all lanes redundantly)
    {
        float di = g_dinv[n];
        float dd = di * di;
        float4 xs = __ldg(&xw4[(size_t)n * 8 + sub]);
        float4 bb = __ldg(&((const float4*)b)[sub]);
        acc.x = fmaf(dd, xs.x, acc.x) + bb.x;
        acc.y = fmaf(dd, xs.y, acc.y) + bb.y;
        acc.z = fmaf(dd, xs.z, acc.z) + bb.z;
        acc.w = fmaf(dd, xs.w, acc.w) + bb.w;
    }

    // transpose to scalar layout: lane = channel
    if (grp == 0) ((float4*)&sh_h[warp][0])[sub] = acc;
    __syncwarp();
    float aS = sh_h[warp][lane];

    if (FUSE_NEXT) {
        float sc = bng[lane] * rsqrtf(1.0f + BN_EPS);
        float h  = fmaxf(fmaf(aS, sc, bnb[lane]), 0.f);
        float o  = 0.f;
        #pragma unroll
        for (int k = 0; k < HID; ++k)
            o = fmaf(__shfl_sync(FULL, h, k), Ws[k * HID + lane], o);
        out_buf(out_which)[(size_t)n * HID + lane] = o;
    } else {
        emb[(size_t)n * HID + lane] = aS;
        int gidx = batch[n];
        atomicAdd(&g_sums[(size_t)gidx * HID + lane], aS);
        if (lane == 0) atomicAdd(&g_cnts[gidx], 1);
    }
}

__global__ void k_pred(const float* __restrict__ Wout,
                       const float* __restrict__ bout,
                       float* __restrict__ pred) {
    int gI = threadIdx.x;
    if (gI >= N_GRAPHS) return;
    float cnt = fmaxf((float)g_cnts[gI], 1.0f);
    float inv = 1.0f / cnt;
    float acc = bout[0];
    #pragma unroll
    for (int k = 0; k < HID; ++k)
        acc = fmaf(g_sums[gI * HID + k] * inv, Wout[k], acc);
    pred[gI] = 1.0f / (1.0f + expf(-acc));
}

// ---------------- launcher ----------------
extern "C" void kernel_launch(void* const* d_in, const int* in_sizes, int n_in,
                              void* d_out, int out_size) {
    const float* x     = (const float*)d_in[0];
    const int*   ei    = (const int*)  d_in[1];
    const float* pos   = (const float*)d_in[2];
    const int*   batch = (const int*)  d_in[3];
    const float* s1    = (const float*)d_in[4];
    const float* s2    = (const float*)d_in[5];
    const float* W1 = (const float*)d_in[6];
    const float* b1 = (const float*)d_in[7];
    const float* W2 = (const float*)d_in[8];
    const float* b2 = (const float*)d_in[9];
    const float* W3 = (const float*)d_in[10];
    const float* b3 = (const float*)d_in[11];
    const float* W4 = (const float*)d_in[12];
    const float* b4 = (const float*)d_in[13];
    const float* g1 = (const float*)d_in[14];
    const float* be1= (const float*)d_in[15];
    const float* g2 = (const float*)d_in[16];
    const float* be2= (const float*)d_in[17];
    const float* g3 = (const float*)d_in[18];
    const float* be3= (const float*)d_in[19];
    const float* Wout = (const float*)d_in[20];
    const float* bout = (const float*)d_in[21];

    float* outp = (float*)d_out;
    float* emb  = outp;                           // [N_NODES, HID]
    float* pred = outp + (size_t)N_NODES * HID;   // [N_GRAPHS]

    const int ZB = (N_NODES + 255) / 256;
    const int NODE_WARP_BLOCKS = (N_NODES * 32 + 255) / 256;

    k_zero <<<ZB, 256>>>();
    k_edgew<<<4096, 256>>>(ei, pos, s1, s2);
    k_dinv <<<ZB, 256>>>();
    k_scanA<<<SCAN_BLOCKS, SCAN_T>>>();
    k_scanB<<<1, 128>>>();
    k_scanC<<<SCAN_BLOCKS, SCAN_T>>>();
    k_build<<<4096, 256>>>(ei);

    k_gemm1<<<NODE_WARP_BLOCKS, 256>>>(x, W1);

    k_gather<1><<<NODE_WARP_BLOCKS, 256>>>(0, 1, b1, g1, be1, W2, nullptr, nullptr);
    k_gather<1><<<NODE_WARP_BLOCKS, 256>>>(1, 0, b2, g2, be2, W3, nullptr, nullptr);
    k_gather<1><<<NODE_WARP_BLOCKS, 256>>>(0, 1, b3, g3, be3, W4, nullptr, nullptr);
    k_gather<0><<<NODE_WARP_BLOCKS, 256>>>(1, 0, b4, nullptr, nullptr, nullptr, emb, batch);

    k_pred<<<1, 256>>>(Wout, bout, pred);
}